// round 14
// baseline (speedup 1.0000x reference)
#include <cuda_runtime.h>
#include <math.h>
#include <stdint.h>

// Problem shapes (fixed for this bench)
#define BB 4
#define TT 512
#define SS 1024
#define HH 768
#define VV 50257

// Copy kernel: TWO CTAs per (b,t) row, 768 threads each.
// 2 CTAs/SM = 1536 thr/SM -> 512 thread slots/SM left free so the pgen side
// chain can co-schedule (R12 showed full-occupancy copy serializes the fork).
#define VLO1   25129                 // half0 = [0,25129), half1 = [25129,50257)
#define VPADH  25136                 // pad(<=3) + 25129, rounded up
#define SMEM_BYTES  (VPADH * 4)
#define NTHR 768

#define NROWS (BB * TT)              // 2048
#define NU    (BB * SS)              // 4096 u rows
#define NUV   (NU + NROWS)           // 6144 projection rows

// Collapsed p_gen projections (produced by prep, consumed by pgen_row).
__device__ float g_u[NU];
__device__ float g_v[NROWS];

// ---------------------------------------------------------------------------
// Kernel A (side stream): projections u[b,s]=src.W1, v[row]=tgt.W2+bias.
// One warp per row, 6144 rows.
// ---------------------------------------------------------------------------
__global__ void pgen_prep_kernel(const float* __restrict__ src,
                                 const float* __restrict__ tgt,
                                 const float* __restrict__ W,
                                 const float* __restrict__ bias)
{
    const int warp = (blockIdx.x * blockDim.x + threadIdx.x) >> 5;
    const int lane = threadIdx.x & 31;
    if (warp >= NUV) return;

    const float4* x;
    const float4* w;
    if (warp < NU) {
        x = reinterpret_cast<const float4*>(src + (size_t)warp * HH);
        w = reinterpret_cast<const float4*>(W);
    } else {
        x = reinterpret_cast<const float4*>(tgt + (size_t)(warp - NU) * HH);
        w = reinterpret_cast<const float4*>(W + HH);
    }
    float acc = 0.f;
    #pragma unroll
    for (int j = lane; j < HH / 4; j += 32) {
        float4 a = x[j], b = w[j];
        acc += a.x * b.x + a.y * b.y + a.z * b.z + a.w * b.w;
    }
    #pragma unroll
    for (int o = 16; o; o >>= 1) acc += __shfl_xor_sync(0xffffffffu, acc, o);
    if (lane == 0) {
        if (warp < NU) g_u[warp] = acc;
        else           g_v[warp - NU] = acc + bias[0];
    }
}

// ---------------------------------------------------------------------------
// Kernel B (side stream): p_gen[row] = sigmoid(attn[row,:].u[b,:] + v[row]).
// One warp per row, 2048 rows.
// ---------------------------------------------------------------------------
__global__ void pgen_row_kernel(const float* __restrict__ attn,
                                float* __restrict__ out_pgen)
{
    const int row  = (blockIdx.x * blockDim.x + threadIdx.x) >> 5;
    const int lane = threadIdx.x & 31;
    if (row >= NROWS) return;
    const int b = row >> 9;

    const float4* ar = reinterpret_cast<const float4*>(attn + (size_t)row * SS);
    const float4* ur = reinterpret_cast<const float4*>(g_u + b * SS);
    float acc = 0.f;
    #pragma unroll
    for (int j = lane; j < SS / 4; j += 32) {
        float4 a = ar[j], u = ur[j];
        acc += a.x * u.x + a.y * u.y + a.z * u.z + a.w * u.w;
    }
    #pragma unroll
    for (int o = 16; o; o >>= 1) acc += __shfl_xor_sync(0xffffffffu, acc, o);
    if (lane == 0) {
        const float zv = acc + g_v[row];
        out_pgen[row] = 1.f / (1.f + __expf(-zv));
    }
}

// ---------------------------------------------------------------------------
// Kernel C (main stream): PURE copy. Two CTAs per (b,t) row, 768 threads:
// zero ~100KB smem accumulator, shared-atomic scatter (tid<256 handle two
// source positions), one TMA bulk-store. No pgen logic.
// ---------------------------------------------------------------------------
__global__ __launch_bounds__(NTHR, 2)
void copy_logits_kernel(const int* __restrict__ ids,
                        const float* __restrict__ attn,
                        float* __restrict__ out_logits)
{
    extern __shared__ float sm[];          // [VPADH] accumulator
    const int row  = blockIdx.x >> 1;      // b*T + t
    const int half = blockIdx.x & 1;
    const int b    = row >> 9;
    const int tid  = threadIdx.x;

    const int lo = half ? VLO1 : 0;
    const int hi = half ? VV   : VLO1;
    const int n  = hi - lo;

    // Global destination of this half-row; 16B phase decides head & pad.
    float* dst = out_logits + (size_t)row * VV + lo;
    const int head = (int)(((16u - ((uint32_t)(uintptr_t)dst & 15u)) & 15u) >> 2);
    const int pad  = (4 - head) & 3;       // sm[pad+head] is 16B-aligned

    // Phase 1: zero the accumulator (vectorized STS.128).
    float4* sm4 = reinterpret_cast<float4*>(sm);
    const float4 z4 = make_float4(0.f, 0.f, 0.f, 0.f);
    #pragma unroll
    for (int i = tid; i < VPADH / 4; i += NTHR) sm4[i] = z4;
    __syncthreads();

    // Phase 2: range-predicated scatter-add over S=1024 positions.
    {
        const float a0  = attn[(size_t)row * SS + tid];
        const int   id0 = ids[b * SS + tid];
        if (id0 >= lo && id0 < hi) atomicAdd(&sm[pad + id0 - lo], a0);
        if (tid < SS - NTHR) {
            const float a1  = attn[(size_t)row * SS + NTHR + tid];
            const int   id1 = ids[b * SS + NTHR + tid];
            if (id1 >= lo && id1 < hi) atomicAdd(&sm[pad + id1 - lo], a1);
        }
    }
    __syncthreads();                       // all atomics complete

    // Phase 3: head/tail scalars + one bulk-async (TMA) copy for the middle.
    const int nvec = (n - head) >> 2;
    const int tail = head + 4 * nvec;

    if (tid < head)     __stcs(dst + tid, sm[pad + tid]);
    if (tid < n - tail) __stcs(dst + tail + tid, sm[pad + tail + tid]);

    if (tid == 0) {
        asm volatile("fence.proxy.async.shared::cta;" ::: "memory");
        uint32_t saddr;
        asm("{ .reg .u64 t; cvta.to.shared.u64 t, %1; cvt.u32.u64 %0, t; }"
            : "=r"(saddr) : "l"(sm + pad + head));
        asm volatile(
            "cp.async.bulk.global.shared::cta.bulk_group [%0], [%1], %2;"
            :: "l"(dst + head), "r"(saddr), "r"(16 * nvec) : "memory");
        asm volatile("cp.async.bulk.commit_group;" ::: "memory");
        asm volatile("cp.async.bulk.wait_group 0;" ::: "memory");
    }
}

// ---------------------------------------------------------------------------
// Launch: fork a side stream inside the capture so the tiny pgen chain
// (prep -> pgen_row) runs CONCURRENTLY with the DRAM-bound copy kernel —
// the 512 free thread slots per SM give it somewhere to run this time.
// ---------------------------------------------------------------------------
extern "C" void kernel_launch(void* const* d_in, const int* in_sizes, int n_in,
                              void* d_out, int out_size)
{
    const int*   ids  = (const int*)  d_in[0];  // [B,S] int32
    const float* attn = (const float*)d_in[1];  // [B,T,S]
    const float* src  = (const float*)d_in[2];  // [B,S,H]
    const float* tgt  = (const float*)d_in[3];  // [B,T,H]
    const float* W    = (const float*)d_in[4];  // [2H,1]
    const float* bias = (const float*)d_in[5];  // [1]

    float* out_pgen   = (float*)d_out;              // [B,T]  (first output)
    float* out_logits = out_pgen + (size_t)BB * TT; // [B,T,V]

    cudaFuncSetAttribute(copy_logits_kernel,
                         cudaFuncAttributeMaxDynamicSharedMemorySize,
                         SMEM_BYTES);

    static cudaStream_t s2 = 0;
    static cudaEvent_t  evF = 0, evJ = 0;
    static int init_state = 0;             // 0=untried, 1=ok, -1=failed
    if (init_state == 0) {
        if (cudaStreamCreateWithFlags(&s2, cudaStreamNonBlocking) == cudaSuccess &&
            cudaEventCreateWithFlags(&evF, cudaEventDisableTiming) == cudaSuccess &&
            cudaEventCreateWithFlags(&evJ, cudaEventDisableTiming) == cudaSuccess)
            init_state = 1;
        else {
            init_state = -1;
            (void)cudaGetLastError();
        }
    }

    if (init_state == 1) {
        // Fork: side stream joins the capture via the event dependency.
        cudaEventRecord(evF, 0);
        cudaStreamWaitEvent(s2, evF, 0);

        pgen_prep_kernel<<<(NUV + 7) / 8, 256, 0, s2>>>(src, tgt, W, bias);
        pgen_row_kernel<<<(NROWS + 7) / 8, 256, 0, s2>>>(attn, out_pgen);
        cudaEventRecord(evJ, s2);

        // Main stream: pure copy kernel, concurrent with the side chain.
        copy_logits_kernel<<<NROWS * 2, NTHR, SMEM_BYTES>>>(ids, attn,
                                                            out_logits);
        // Join before kernel_launch returns.
        cudaStreamWaitEvent(0, evJ, 0);
    } else {
        // Serial fallback.
        pgen_prep_kernel<<<(NUV + 7) / 8, 256>>>(src, tgt, W, bias);
        pgen_row_kernel<<<(NROWS + 7) / 8, 256>>>(attn, out_pgen);
        copy_logits_kernel<<<NROWS * 2, NTHR, SMEM_BYTES>>>(ids, attn,
                                                            out_logits);
    }
}

// round 15
// speedup vs baseline: 1.1092x; 1.1092x over previous
#include <cuda_runtime.h>
#include <math.h>
#include <stdint.h>

// Problem shapes (fixed for this bench)
#define BB 4
#define TT 512
#define SS 1024
#define HH 768
#define VV 50257

// Copy kernel: TWO CTAs per (b,t) row, 1024 threads (R6 proven shape).
#define VLO1   25129                 // half0 = [0,25129), half1 = [25129,50257)
#define VPADH  25136                 // pad(<=3) + 25129, rounded up
#define SMEM_BYTES  (VPADH * 4)
#define NTHR 1024

#define NROWS (BB * TT)              // 2048
#define NU    (BB * SS)              // 4096 u rows
#define NUV   (NU + NROWS)           // 6144 projection rows

// Collapsed p_gen projections. Produced inside the copy kernel (warps 0-1 of
// CTAs 0..3071, no synchronization needed), consumed by pgen_row_kernel
// across the kernel boundary.
__device__ float g_u[NU];
__device__ float g_v[NROWS];

// ---------------------------------------------------------------------------
// Kernel 1: copy + embedded projections.
// Two CTAs per (b,t) row, each owning half the vocab:
//   warps 0-1 (CTAs 0..3071): one projection row each (u or v) — runs while
//                             warps 2-31 zero the ~100KB smem accumulator.
//   then: shared-atomic scatter, one TMA bulk-store per half-row.
// ---------------------------------------------------------------------------
__global__ __launch_bounds__(NTHR, 2)
void copy_logits_kernel(const int* __restrict__ ids,
                        const float* __restrict__ attn,
                        const float* __restrict__ src,
                        const float* __restrict__ tgt,
                        const float* __restrict__ W,
                        const float* __restrict__ bias,
                        float* __restrict__ out_logits)
{
    extern __shared__ float sm[];          // [VPADH] accumulator
    const int cid  = blockIdx.x;           // 0..4095
    const int row  = cid >> 1;             // b*T + t
    const int half = cid & 1;
    const int b    = row >> 9;
    const int tid  = threadIdx.x;
    const int wid  = tid >> 5;
    const int lane = tid & 31;

    const int lo = half ? VLO1 : 0;
    const int hi = half ? VV   : VLO1;
    const int n  = hi - lo;

    // Global destination of this half-row; 16B phase decides head & pad.
    float* dst = out_logits + (size_t)row * VV + lo;
    const int head = (int)(((16u - ((uint32_t)(uintptr_t)dst & 15u)) & 15u) >> 2);
    const int pad  = (4 - head) & 3;       // sm[pad+head] is 16B-aligned

    // Phase 1 (split roles):
    //  warps 0-1: projection row pr = 2*cid + wid (CTAs 0..3071 cover 0..6143)
    //  warps 2-31: zero the accumulator (vectorized STS.128).
    const int pr = 2 * cid + wid;
    if (wid < 2 && pr < NUV) {
        const float4* x;
        const float4* w;
        if (pr < NU) {
            x = reinterpret_cast<const float4*>(src + (size_t)pr * HH);
            w = reinterpret_cast<const float4*>(W);
        } else {
            x = reinterpret_cast<const float4*>(tgt + (size_t)(pr - NU) * HH);
            w = reinterpret_cast<const float4*>(W + HH);
        }
        float acc = 0.f;
        #pragma unroll
        for (int j = lane; j < HH / 4; j += 32) {
            float4 aa = x[j], bb = w[j];
            acc += aa.x * bb.x + aa.y * bb.y + aa.z * bb.z + aa.w * bb.w;
        }
        #pragma unroll
        for (int o = 16; o; o >>= 1) acc += __shfl_xor_sync(0xffffffffu, acc, o);
        if (lane == 0) {
            if (pr < NU) g_u[pr] = acc;
            else         g_v[pr - NU] = acc + bias[0];
        }
    }
    if (wid >= 2 || pr >= NUV) {
        float4* sm4 = reinterpret_cast<float4*>(sm);
        const float4 z4 = make_float4(0.f, 0.f, 0.f, 0.f);
        // threads 64..1023 (or all, for non-prep CTAs) cover the zero-fill
        const int base = (wid < 2) ? tid : (tid - 64);
        const int step = (2 * cid < NUV) ? (NTHR - 64) : NTHR;
        // For prep CTAs: warps 2-31 => indices (tid-64) stepping 960.
        // For non-prep CTAs (cid>=3072): all 1024 threads, step 1024.
        if (2 * cid < NUV) {
            if (wid >= 2)
                for (int i = tid - 64; i < VPADH / 4; i += NTHR - 64) sm4[i] = z4;
        } else {
            for (int i = tid; i < VPADH / 4; i += NTHR) sm4[i] = z4;
        }
        (void)base; (void)step;
    }
    __syncthreads();

    // Phase 2: range-predicated scatter-add. Exactly S=1024 threads, 1 each.
    const float a  = attn[(size_t)row * SS + tid];
    const int   id = ids[b * SS + tid];
    if (id >= lo && id < hi) atomicAdd(&sm[pad + id - lo], a);
    __syncthreads();                       // all atomics complete

    // Phase 3: head/tail scalars + one bulk-async (TMA) copy for the middle.
    const int nvec = (n - head) >> 2;
    const int tail = head + 4 * nvec;

    if (tid < head)     __stcs(dst + tid, sm[pad + tid]);
    if (tid < n - tail) __stcs(dst + tail + tid, sm[pad + tail + tid]);

    if (tid == 0) {
        asm volatile("fence.proxy.async.shared::cta;" ::: "memory");
        uint32_t saddr;
        asm("{ .reg .u64 t; cvta.to.shared.u64 t, %1; cvt.u32.u64 %0, t; }"
            : "=r"(saddr) : "l"(sm + pad + head));
        asm volatile(
            "cp.async.bulk.global.shared::cta.bulk_group [%0], [%1], %2;"
            :: "l"(dst + head), "r"(saddr), "r"(16 * nvec) : "memory");
        asm volatile("cp.async.bulk.commit_group;" ::: "memory");
        asm volatile("cp.async.bulk.wait_group 0;" ::: "memory");
    }
}

// ---------------------------------------------------------------------------
// Kernel 2 (PDL): p_gen[row] = sigmoid(attn[row,:].u[b,:] + v[row]).
// One warp per row. Prefetches its attn row into registers BEFORE the grid
// dependency sync, so only the u-dot serializes behind the copy kernel tail.
// ---------------------------------------------------------------------------
__global__ void pgen_row_kernel(const float* __restrict__ attn,
                                float* __restrict__ out_pgen)
{
    const int row  = (blockIdx.x * blockDim.x + threadIdx.x) >> 5;
    const int lane = threadIdx.x & 31;
    if (row >= NROWS) {
#if __CUDA_ARCH__ >= 900
        cudaGridDependencySynchronize();
#endif
        return;
    }
    const int b = row >> 9;

    // Prefetch attn row (independent of the copy kernel's outputs).
    const float4* ar = reinterpret_cast<const float4*>(attn + (size_t)row * SS);
    float4 a[8];
    #pragma unroll
    for (int k = 0; k < 8; k++) a[k] = ar[lane + 32 * k];

#if __CUDA_ARCH__ >= 900
    cudaGridDependencySynchronize();       // u, v now valid
#endif

    const float4* ur = reinterpret_cast<const float4*>(g_u + b * SS);
    float acc = 0.f;
    #pragma unroll
    for (int k = 0; k < 8; k++) {
        float4 u = ur[lane + 32 * k];
        acc += a[k].x * u.x + a[k].y * u.y + a[k].z * u.z + a[k].w * u.w;
    }
    #pragma unroll
    for (int o = 16; o; o >>= 1) acc += __shfl_xor_sync(0xffffffffu, acc, o);
    if (lane == 0) {
        const float zv = acc + g_v[row];
        out_pgen[row] = 1.f / (1.f + __expf(-zv));
    }
}

// ---------------------------------------------------------------------------
// Launch: copy kernel (with embedded prep), then pgen_row via PDL.
// ---------------------------------------------------------------------------
extern "C" void kernel_launch(void* const* d_in, const int* in_sizes, int n_in,
                              void* d_out, int out_size)
{
    const int*   ids  = (const int*)  d_in[0];  // [B,S] int32
    const float* attn = (const float*)d_in[1];  // [B,T,S]
    const float* src  = (const float*)d_in[2];  // [B,S,H]
    const float* tgt  = (const float*)d_in[3];  // [B,T,H]
    const float* W    = (const float*)d_in[4];  // [2H,1]
    const float* bias = (const float*)d_in[5];  // [1]

    float* out_pgen   = (float*)d_out;              // [B,T]  (first output)
    float* out_logits = out_pgen + (size_t)BB * TT; // [B,T,V]

    cudaFuncSetAttribute(copy_logits_kernel,
                         cudaFuncAttributeMaxDynamicSharedMemorySize,
                         SMEM_BYTES);

    copy_logits_kernel<<<NROWS * 2, NTHR, SMEM_BYTES>>>(
        ids, attn, src, tgt, W, bias, out_logits);

    // pgen_row with PDL so its attn prefetch overlaps the copy kernel tail.
    cudaLaunchConfig_t cfg = {};
    cfg.gridDim  = dim3((NROWS * 32 + 255) / 256, 1, 1);
    cfg.blockDim = dim3(256, 1, 1);
    cfg.stream   = 0;
    cudaLaunchAttribute attr[1];
    attr[0].id = cudaLaunchAttributeProgrammaticStreamSerialization;
    attr[0].val.programmaticStreamSerializationAllowed = 1;
    cfg.attrs    = attr;
    cfg.numAttrs = 1;

    cudaError_t e = cudaLaunchKernelEx(&cfg, pgen_row_kernel, attn, out_pgen);
    if (e != cudaSuccess) {
        (void)cudaGetLastError();
        pgen_row_kernel<<<(NROWS * 32 + 255) / 256, 256>>>(attn, out_pgen);
    }
}

// round 16
// speedup vs baseline: 1.4107x; 1.2718x over previous
#include <cuda_runtime.h>
#include <math.h>
#include <stdint.h>

// Problem shapes (fixed for this bench)
#define BB 4
#define TT 512
#define SS 1024
#define HH 768
#define VV 50257

// Vocab split: two CTAs per (b,t) row (proven fastest copy shape).
#define VLO1   25129                 // half0 = [0,25129), half1 = [25129,50257)
#define VPADH  25136                 // pad(<=3) + 25129, rounded up
#define SMEM_FLOATS (VPADH + 32)
#define SMEM_BYTES  (SMEM_FLOATS * 4)

#define NROWS (BB * TT)              // 2048
#define NU    (BB * SS)              // 4096 u rows
#define NUV   (NU + NROWS)           // 6144 projection rows

// Scratch for the collapsed p_gen projections (device globals: no allocation).
__device__ float g_u[NU];            // u[b,s] = src[b,s,:] . W_pgen[:H]
__device__ float g_v[NROWS];         // v[b,t] = tgt[b,t,:] . W_pgen[H:] + bias

// ---------------------------------------------------------------------------
// Kernel 1: projections, TWO rows per warp (interleaved loads -> 2x MLP; the
// R12 profile showed this kernel latency-bound at 27% DRAM). 384 blocks.
// Triggers programmatic launch completion at entry for PDL overlap.
// ---------------------------------------------------------------------------
__global__ __launch_bounds__(256)
void pgen_prep_kernel(const float* __restrict__ src,
                      const float* __restrict__ tgt,
                      const float* __restrict__ W,
                      const float* __restrict__ bias)
{
#if __CUDA_ARCH__ >= 900
    cudaTriggerProgrammaticLaunchCompletion();
#endif
    const int warp = (blockIdx.x * blockDim.x + threadIdx.x) >> 5;
    const int lane = threadIdx.x & 31;
    const int r0 = 2 * warp;                // rows r0, r0+1
    if (r0 >= NUV) return;

    // Row pointer + weight selector for a projection row index.
    auto rowptr = [&](int rr, const float4*& x, const float4*& w) {
        if (rr < NU) {
            x = reinterpret_cast<const float4*>(src + (size_t)rr * HH);
            w = reinterpret_cast<const float4*>(W);
        } else {
            x = reinterpret_cast<const float4*>(tgt + (size_t)(rr - NU) * HH);
            w = reinterpret_cast<const float4*>(W + HH);
        }
    };

    const float4 *x0, *w0, *x1, *w1;
    rowptr(r0, x0, w0);
    const bool two = (r0 + 1) < NUV;
    rowptr(two ? r0 + 1 : r0, x1, w1);

    float acc0 = 0.f, acc1 = 0.f;
    #pragma unroll
    for (int j = lane; j < HH / 4; j += 32) {
        float4 a0 = x0[j];                  // interleaved independent loads
        float4 a1 = x1[j];
        float4 b0 = w0[j];
        float4 b1 = w1[j];
        acc0 += a0.x * b0.x + a0.y * b0.y + a0.z * b0.z + a0.w * b0.w;
        acc1 += a1.x * b1.x + a1.y * b1.y + a1.z * b1.z + a1.w * b1.w;
    }
    #pragma unroll
    for (int o = 16; o; o >>= 1) {
        acc0 += __shfl_xor_sync(0xffffffffu, acc0, o);
        acc1 += __shfl_xor_sync(0xffffffffu, acc1, o);
    }
    if (lane == 0) {
        if (r0 < NU) g_u[r0] = acc0;
        else         g_v[r0 - NU] = acc0 + bias[0];
        if (two) {
            const int r1 = r0 + 1;
            if (r1 < NU) g_u[r1] = acc1;
            else         g_v[r1 - NU] = acc1 + bias[0];
        }
    }
}

// ---------------------------------------------------------------------------
// Kernel 2 (exact R7 shape, 16 regs): two CTAs per (b,t) row.
//   Phase 1: zero ~100KB smem accumulator (STS.128)
//   Phase 2: range-predicated shared atomicAdd scatter
//   Phase 3: ONE bulk-async (TMA) copy smem -> gmem for the half-row
//   Phase 4 (half 0): grid-dep sync on prep, fused p_gen reduction —
//            overlapped with this CTA's own TMA drain.
// ---------------------------------------------------------------------------
__global__ __launch_bounds__(1024, 2)
void copy_logits_kernel(const int* __restrict__ ids,
                        const float* __restrict__ attn,
                        float* __restrict__ out_pgen,
                        float* __restrict__ out_logits)
{
    extern __shared__ float sm[];          // [VPADH] accumulator + [32] reduce
    const int row  = blockIdx.x >> 1;      // b*T + t
    const int half = blockIdx.x & 1;
    const int b    = row >> 9;
    const int tid  = threadIdx.x;

    const int lo = half ? VLO1 : 0;
    const int hi = half ? VV   : VLO1;
    const int n  = hi - lo;

    // Global destination of this half-row; 16B phase decides head & pad.
    float* dst = out_logits + (size_t)row * VV + lo;
    const int head = (int)(((16u - ((uint32_t)(uintptr_t)dst & 15u)) & 15u) >> 2);
    const int pad  = (4 - head) & 3;       // sm[pad+head] is 16B-aligned

    // Phase 1: zero the accumulator (vectorized STS.128).
    float4* sm4 = reinterpret_cast<float4*>(sm);
    const float4 z4 = make_float4(0.f, 0.f, 0.f, 0.f);
    #pragma unroll
    for (int i = tid; i < VPADH / 4; i += 1024) sm4[i] = z4;
    __syncthreads();

    // Phase 2: range-predicated scatter-add. Exactly S=1024 threads, 1 each.
    const float a  = attn[(size_t)row * SS + tid];
    const int   id = ids[b * SS + tid];
    if (id >= lo && id < hi) atomicAdd(&sm[pad + id - lo], a);
    __syncthreads();                       // all atomics complete

    // Phase 3: head/tail scalars + one bulk-async copy for the aligned middle.
    const int nvec = (n - head) >> 2;
    const int tail = head + 4 * nvec;

    if (tid < head)     __stcs(dst + tid, sm[pad + tid]);
    if (tid < n - tail) __stcs(dst + tail + tid, sm[pad + tail + tid]);

    if (tid == 0) {
        asm volatile("fence.proxy.async.shared::cta;" ::: "memory");
        uint32_t saddr;
        asm("{ .reg .u64 t; cvta.to.shared.u64 t, %1; cvt.u32.u64 %0, t; }"
            : "=r"(saddr) : "l"(sm + pad + head));
        asm volatile(
            "cp.async.bulk.global.shared::cta.bulk_group [%0], [%1], %2;"
            :: "l"(dst + head), "r"(saddr), "r"(16 * nvec) : "memory");
        asm volatile("cp.async.bulk.commit_group;" ::: "memory");
    }

    // Phase 4: fused p_gen = sigmoid(attn . u + v), half-0 CTAs only.
    // Runs while this CTA's TMA drain is in flight. Requires prep complete.
    if (half == 0) {
#if __CUDA_ARCH__ >= 900
        cudaGridDependencySynchronize();
#endif
        float part = a * g_u[b * SS + tid];
        #pragma unroll
        for (int o = 16; o; o >>= 1) part += __shfl_xor_sync(0xffffffffu, part, o);
        float* red = sm + VPADH;
        if ((tid & 31) == 0) red[tid >> 5] = part;
        __syncthreads();
        if (tid < 32) {
            float x = red[tid];
            #pragma unroll
            for (int o = 16; o; o >>= 1) x += __shfl_xor_sync(0xffffffffu, x, o);
            if (tid == 0) {
                const float zv = x + g_v[row];
                out_pgen[row] = 1.f / (1.f + __expf(-zv));
            }
        }
    }

    if (tid == 0)
        asm volatile("cp.async.bulk.wait_group 0;" ::: "memory");
}

// ---------------------------------------------------------------------------
// Launch: prep, then copy with Programmatic Dependent Launch so copy's
// g_u-independent phases overlap prep. Fallback to plain launch on error.
// ---------------------------------------------------------------------------
extern "C" void kernel_launch(void* const* d_in, const int* in_sizes, int n_in,
                              void* d_out, int out_size)
{
    const int*   ids  = (const int*)  d_in[0];  // [B,S] int32
    const float* attn = (const float*)d_in[1];  // [B,T,S]
    const float* src  = (const float*)d_in[2];  // [B,S,H]
    const float* tgt  = (const float*)d_in[3];  // [B,T,H]
    const float* W    = (const float*)d_in[4];  // [2H,1]
    const float* bias = (const float*)d_in[5];  // [1]

    float* out_pgen   = (float*)d_out;              // [B,T]  (first output)
    float* out_logits = out_pgen + (size_t)BB * TT; // [B,T,V]

    cudaFuncSetAttribute(copy_logits_kernel,
                         cudaFuncAttributeMaxDynamicSharedMemorySize,
                         SMEM_BYTES);

    // 6144 rows, 2 per warp, 8 warps per block -> 384 blocks.
    pgen_prep_kernel<<<NUV / 16, 256>>>(src, tgt, W, bias);

    // Copy kernel with PDL (programmatic stream serialization).
    cudaLaunchConfig_t cfg = {};
    cfg.gridDim          = dim3(NROWS * 2, 1, 1);
    cfg.blockDim         = dim3(1024, 1, 1);
    cfg.dynamicSmemBytes = SMEM_BYTES;
    cfg.stream           = 0;
    cudaLaunchAttribute attr[1];
    attr[0].id = cudaLaunchAttributeProgrammaticStreamSerialization;
    attr[0].val.programmaticStreamSerializationAllowed = 1;
    cfg.attrs    = attr;
    cfg.numAttrs = 1;

    cudaError_t e = cudaLaunchKernelEx(&cfg, copy_logits_kernel,
                                       ids, attn, out_pgen, out_logits);
    if (e != cudaSuccess) {
        (void)cudaGetLastError();   // clear; fall back to plain launch
        copy_logits_kernel<<<NROWS * 2, 1024, SMEM_BYTES>>>(ids, attn,
                                                            out_pgen,
                                                            out_logits);
    }
}